// round 7
// baseline (speedup 1.0000x reference)
#include <cuda_runtime.h>
#include <math.h>

#define D_MODEL  1024
#define N_HEADS  16
#define HEAD_DIM 64
#define BATCH    4
#define SEQ      2048
#define M_TOK    (BATCH * SEQ)   // 8192

// Scratch (allocation-free rule: __device__ globals)
__device__ float g_qkv[(size_t)M_TOK * 3 * D_MODEL];  // 96 MB
__device__ float g_att[(size_t)M_TOK * D_MODEL];      // 32 MB

// ---------------------------------------------------------------------------
// SGEMM: C[M,N] = A[M,K] @ W[N,K]^T (verified == naive in R3)
// ---------------------------------------------------------------------------
__global__ __launch_bounds__(256) void sgemm_nt_128x128(
    const float* __restrict__ A, const float* __restrict__ W,
    float* __restrict__ C, int M, int N, int K)
{
    __shared__ float As[32][132];
    __shared__ float Bs[32][132];

    const int tid = threadIdx.x;
    const int tx  = tid & 15;
    const int ty  = tid >> 4;
    const size_t arow0 = (size_t)blockIdx.y * 128;
    const size_t brow0 = (size_t)blockIdx.x * 128;
    const float* Ab = A + arow0 * (size_t)K;
    const float* Wb = W + brow0 * (size_t)K;

    float acc[8][8];
    #pragma unroll
    for (int i = 0; i < 8; i++)
        #pragma unroll
        for (int j = 0; j < 8; j++) acc[i][j] = 0.f;

    for (int k0 = 0; k0 < K; k0 += 32) {
        #pragma unroll
        for (int i = 0; i < 4; i++) {
            int idx = tid + i * 256;
            int row = idx >> 3;
            int c4  = (idx & 7) * 4;
            float4 va = *(const float4*)(Ab + (size_t)row * K + k0 + c4);
            As[c4 + 0][row] = va.x; As[c4 + 1][row] = va.y;
            As[c4 + 2][row] = va.z; As[c4 + 3][row] = va.w;
            float4 vb = *(const float4*)(Wb + (size_t)row * K + k0 + c4);
            Bs[c4 + 0][row] = vb.x; Bs[c4 + 1][row] = vb.y;
            Bs[c4 + 2][row] = vb.z; Bs[c4 + 3][row] = vb.w;
        }
        __syncthreads();
        #pragma unroll
        for (int kk = 0; kk < 32; kk++) {
            float a[8], b[8];
            *(float4*)&a[0] = *(const float4*)&As[kk][ty * 8];
            *(float4*)&a[4] = *(const float4*)&As[kk][ty * 8 + 4];
            *(float4*)&b[0] = *(const float4*)&Bs[kk][tx * 8];
            *(float4*)&b[4] = *(const float4*)&Bs[kk][tx * 8 + 4];
            #pragma unroll
            for (int i = 0; i < 8; i++)
                #pragma unroll
                for (int j = 0; j < 8; j++)
                    acc[i][j] += a[i] * b[j];
        }
        __syncthreads();
    }

    float* Cb = C + (arow0 + ty * 8) * (size_t)N + brow0 + tx * 8;
    #pragma unroll
    for (int i = 0; i < 8; i++) {
        float4 v0 = make_float4(acc[i][0], acc[i][1], acc[i][2], acc[i][3]);
        float4 v1 = make_float4(acc[i][4], acc[i][5], acc[i][6], acc[i][7]);
        *(float4*)(Cb + (size_t)i * N)     = v0;
        *(float4*)(Cb + (size_t)i * N + 4) = v1;
    }
}

// ---------------------------------------------------------------------------
// RoPE in-place, SIGN-FLIPPED NeoX (decoded winner from R6 multiplex):
//   x1' = x1*cos + x2*sin ;  x2' = x2*cos - x1*sin,  pairs (i, i+32),
//   theta_i = 10000^(-i/32). Double-precision transcendentals.
// One thread per (token, q/k, head, freq i<32).
// ---------------------------------------------------------------------------
__global__ __launch_bounds__(256) void rope_kernel()
{
    int idx = blockIdx.x * blockDim.x + threadIdx.x;   // < M_TOK * 1024
    int i   = idx & 31;
    int h   = (idx >> 5) & 15;
    int qk  = (idx >> 9) & 1;
    int tok = idx >> 10;
    int t   = tok & (SEQ - 1);

    double th = pow(10000.0, -(double)i / 32.0);
    float  f  = (float)t * (float)th;
    double cd, sd;
    sincos((double)f, &cd, &sd);
    float c = (float)cd, s = (float)sd;

    float* base = g_qkv + (size_t)tok * 3072 + qk * 1024 + h * 64 + i;
    float x1 = base[0];
    float x2 = base[32];
    base[0]  = x1 * c + x2 * s;
    base[32] = x2 * c - x1 * s;
}

// ---------------------------------------------------------------------------
// Flash attention (R2 implementation, twice-verified). NH=16, HD=64.
// Grid: (SEQ/8, BATCH*N_HEADS), 256 threads = 8 warps; warp owns a query row.
// ---------------------------------------------------------------------------
__global__ __launch_bounds__(256) void attn_kernel()
{
    __shared__ float Qs[8][68];
    __shared__ float Ks[32][68];
    __shared__ float Vs[32][68];

    const int tid  = threadIdx.x;
    const int w    = tid >> 5;
    const int lane = tid & 31;
    const int q0   = blockIdx.x * 8;
    const int bh   = blockIdx.y;
    const int b    = bh >> 4;
    const int h    = bh & 15;
    const int qpos = q0 + w;
    const size_t qk_base = (size_t)b * SEQ * 3072;

    if (tid < 128) {
        int row = tid >> 4;
        int d4  = (tid & 15) * 4;
        *(float4*)&Qs[row][d4] =
            *(const float4*)(g_qkv + qk_base + (size_t)(q0 + row) * 3072 + h * 64 + d4);
    }

    float m = -1e30f, l = 0.f, o0 = 0.f, o1 = 0.f;
    const int nch = ((q0 + 7) >> 5) + 1;

    for (int ch = 0; ch < nch; ch++) {
        const int j0 = ch * 32;
        __syncthreads();
        #pragma unroll
        for (int i = 0; i < 2; i++) {
            int idx = tid + i * 256;
            int row = idx >> 4;
            int d4  = (idx & 15) * 4;
            const float* kp = g_qkv + qk_base + (size_t)(j0 + row) * 3072
                              + 1024 + h * 64 + d4;
            *(float4*)&Ks[row][d4] = *(const float4*)kp;
            *(float4*)&Vs[row][d4] = *(const float4*)(kp + 1024);
        }
        __syncthreads();

        float s = 0.f;
        #pragma unroll
        for (int d4 = 0; d4 < 16; d4++) {
            float4 q = *(const float4*)&Qs[w][d4 * 4];
            float4 k = *(const float4*)&Ks[lane][d4 * 4];
            s += q.x * k.x + q.y * k.y + q.z * k.z + q.w * k.w;
        }
        s = (j0 + lane <= qpos) ? s * 0.125f : -1e30f;

        float mt = s;
        #pragma unroll
        for (int off = 16; off > 0; off >>= 1)
            mt = fmaxf(mt, __shfl_xor_sync(0xffffffffu, mt, off));

        float m_new = fmaxf(m, mt);
        float alpha = expf(m - m_new);
        float p     = expf(s - m_new);

        float lsum = p;
        #pragma unroll
        for (int off = 16; off > 0; off >>= 1)
            lsum += __shfl_xor_sync(0xffffffffu, lsum, off);

        l  = l * alpha + lsum;
        m  = m_new;
        o0 *= alpha;
        o1 *= alpha;

        #pragma unroll
        for (int jj = 0; jj < 32; jj++) {
            float pj = __shfl_sync(0xffffffffu, p, jj);
            float2 v = *(const float2*)&Vs[jj][lane * 2];
            o0 += pj * v.x;
            o1 += pj * v.y;
        }
    }

    float inv = 1.0f / l;
    float* dst = g_att + ((size_t)b * SEQ + qpos) * 1024 + h * 64 + lane * 2;
    dst[0] = o0 * inv;
    dst[1] = o1 * inv;
}

// ---------------------------------------------------------------------------
extern "C" void kernel_launch(void* const* d_in, const int* in_sizes, int n_in,
                              void* d_out, int out_size)
{
    const float* x     = (const float*)d_in[0];
    const float* w_qkv = (const float*)d_in[1];
    const float* w_out = (const float*)d_in[2];
    for (int i = 0; i < n_in; i++) {
        if      (in_sizes[i] == M_TOK * D_MODEL)       x     = (const float*)d_in[i];
        else if (in_sizes[i] == 3 * D_MODEL * D_MODEL) w_qkv = (const float*)d_in[i];
        else if (in_sizes[i] == D_MODEL * D_MODEL)     w_out = (const float*)d_in[i];
    }
    float* out = (float*)d_out;

    float *qkv = nullptr, *att = nullptr;
    cudaGetSymbolAddress((void**)&qkv, g_qkv);
    cudaGetSymbolAddress((void**)&att, g_att);

    // 1) QKV projection
    sgemm_nt_128x128<<<dim3(3 * D_MODEL / 128, M_TOK / 128), 256>>>(
        x, w_qkv, qkv, M_TOK, 3 * D_MODEL, D_MODEL);

    // 2) Sign-flipped NeoX RoPE (all batches)
    rope_kernel<<<(M_TOK * 2 * N_HEADS * 32) / 256, 256>>>();

    // 3) Causal flash attention
    attn_kernel<<<dim3(SEQ / 8, BATCH * N_HEADS), 256>>>();

    // 4) Output projection
    sgemm_nt_128x128<<<dim3(D_MODEL / 128, M_TOK / 128), 256>>>(
        att, w_out, out, M_TOK, D_MODEL, D_MODEL);
}

// round 8
// speedup vs baseline: 1.3972x; 1.3972x over previous
#include <cuda_runtime.h>
#include <math.h>

#define D_MODEL  1024
#define N_HEADS  16
#define HEAD_DIM 64
#define BATCH    4
#define SEQ      2048
#define M_TOK    (BATCH * SEQ)   // 8192

// Scratch (allocation-free rule: __device__ globals)
__device__ float g_qkv[(size_t)M_TOK * 3 * D_MODEL];  // 96 MB
__device__ float g_att[(size_t)M_TOK * D_MODEL];      // 32 MB

// ---------------------------------------------------------------------------
// SGEMM: C[M,N] = A[M,K] @ W[N,K]^T (verified == naive in R3)
// ---------------------------------------------------------------------------
__global__ __launch_bounds__(256) void sgemm_nt_128x128(
    const float* __restrict__ A, const float* __restrict__ W,
    float* __restrict__ C, int M, int N, int K)
{
    __shared__ float As[32][132];
    __shared__ float Bs[32][132];

    const int tid = threadIdx.x;
    const int tx  = tid & 15;
    const int ty  = tid >> 4;
    const size_t arow0 = (size_t)blockIdx.y * 128;
    const size_t brow0 = (size_t)blockIdx.x * 128;
    const float* Ab = A + arow0 * (size_t)K;
    const float* Wb = W + brow0 * (size_t)K;

    float acc[8][8];
    #pragma unroll
    for (int i = 0; i < 8; i++)
        #pragma unroll
        for (int j = 0; j < 8; j++) acc[i][j] = 0.f;

    for (int k0 = 0; k0 < K; k0 += 32) {
        #pragma unroll
        for (int i = 0; i < 4; i++) {
            int idx = tid + i * 256;
            int row = idx >> 3;
            int c4  = (idx & 7) * 4;
            float4 va = *(const float4*)(Ab + (size_t)row * K + k0 + c4);
            As[c4 + 0][row] = va.x; As[c4 + 1][row] = va.y;
            As[c4 + 2][row] = va.z; As[c4 + 3][row] = va.w;
            float4 vb = *(const float4*)(Wb + (size_t)row * K + k0 + c4);
            Bs[c4 + 0][row] = vb.x; Bs[c4 + 1][row] = vb.y;
            Bs[c4 + 2][row] = vb.z; Bs[c4 + 3][row] = vb.w;
        }
        __syncthreads();
        #pragma unroll
        for (int kk = 0; kk < 32; kk++) {
            float a[8], b[8];
            *(float4*)&a[0] = *(const float4*)&As[kk][ty * 8];
            *(float4*)&a[4] = *(const float4*)&As[kk][ty * 8 + 4];
            *(float4*)&b[0] = *(const float4*)&Bs[kk][tx * 8];
            *(float4*)&b[4] = *(const float4*)&Bs[kk][tx * 8 + 4];
            #pragma unroll
            for (int i = 0; i < 8; i++)
                #pragma unroll
                for (int j = 0; j < 8; j++)
                    acc[i][j] += a[i] * b[j];
        }
        __syncthreads();
    }

    float* Cb = C + (arow0 + ty * 8) * (size_t)N + brow0 + tx * 8;
    #pragma unroll
    for (int i = 0; i < 8; i++) {
        float4 v0 = make_float4(acc[i][0], acc[i][1], acc[i][2], acc[i][3]);
        float4 v1 = make_float4(acc[i][4], acc[i][5], acc[i][6], acc[i][7]);
        *(float4*)(Cb + (size_t)i * N)     = v0;
        *(float4*)(Cb + (size_t)i * N + 4) = v1;
    }
}

// ---------------------------------------------------------------------------
// RoPE in-place, sign-flipped NeoX (decoded in R6, verified in R7):
//   x1' = x1*cos + x2*sin ;  x2' = x2*cos - x1*sin,  pairs (i, i+32).
// ---------------------------------------------------------------------------
__global__ __launch_bounds__(256) void rope_kernel()
{
    int idx = blockIdx.x * blockDim.x + threadIdx.x;
    int i   = idx & 31;
    int h   = (idx >> 5) & 15;
    int qk  = (idx >> 9) & 1;
    int tok = idx >> 10;
    int t   = tok & (SEQ - 1);

    double th = pow(10000.0, -(double)i / 32.0);
    float  f  = (float)t * (float)th;
    double cd, sd;
    sincos((double)f, &cd, &sd);
    float c = (float)cd, s = (float)sd;

    float* base = g_qkv + (size_t)tok * 3072 + qk * 1024 + h * 64 + i;
    float x1 = base[0];
    float x2 = base[32];
    base[0]  = x1 * c + x2 * s;
    base[32] = x2 * c - x1 * s;
}

// ---------------------------------------------------------------------------
// Flash attention v2 — GEMM-style register blocking.
// Grid: (SEQ/64, BATCH*N_HEADS), 256 threads as 16x16 (ty -> 4 q-rows,
// tx -> 4 key-cols / 4 out-dims). BQ=64, BK=64, HD=64.
// smem: Qs[64][64] ([d][r]), KP[64][64] (K as [d][c], then P as [k][r]),
//       Vs[64][64] ([k][d]) = exactly 48 KB static.
// Per chunk: S = Q.K^T (reg 4x4), online softmax (16-lane shfl groups),
//            P via smem, O += P.V (reg 4x4).
// ---------------------------------------------------------------------------
__global__ __launch_bounds__(256) void attn_v2()
{
    __shared__ float Qs[64][64];   // [d][r]
    __shared__ float KP[64][64];   // phase 1: K [d][c]; phase 2: P [k][r]
    __shared__ float Vs[64][64];   // [k][d]

    const int tid = threadIdx.x;
    const int tx  = tid & 15;       // key cols / out dims (x4)
    const int ty  = tid >> 4;       // q rows (x4)
    const int bx  = blockIdx.x;
    const int bh  = blockIdx.y;
    const int b   = bh >> 4;
    const int h   = bh & 15;
    const int q0  = bx * 64;
    const size_t base = (size_t)b * SEQ * 3072;

    // Load Q tile transposed: Qs[d][r]
    #pragma unroll
    for (int i = 0; i < 4; i++) {
        int idx = tid + i * 256;
        int r   = idx >> 4;
        int d4  = (idx & 15) * 4;
        float4 v = *(const float4*)(g_qkv + base + (size_t)(q0 + r) * 3072 + h * 64 + d4);
        Qs[d4 + 0][r] = v.x; Qs[d4 + 1][r] = v.y;
        Qs[d4 + 2][r] = v.z; Qs[d4 + 3][r] = v.w;
    }

    float o[4][4];
    float m[4], l[4];
    #pragma unroll
    for (int i = 0; i < 4; i++) {
        m[i] = -1e30f; l[i] = 0.f;
        #pragma unroll
        for (int j = 0; j < 4; j++) o[i][j] = 0.f;
    }

    for (int kb = 0; kb <= bx; kb++) {
        const int j0 = kb * 64;
        __syncthreads();   // previous P fully consumed / Q visible (first iter)

        // Load K (transposed -> KP[d][c]) and V (straight -> Vs[c][d])
        #pragma unroll
        for (int i = 0; i < 4; i++) {
            int idx = tid + i * 256;
            int c   = idx >> 4;
            int d4  = (idx & 15) * 4;
            const float* kp = g_qkv + base + (size_t)(j0 + c) * 3072 + 1024 + h * 64 + d4;
            float4 kv = *(const float4*)kp;
            KP[d4 + 0][c] = kv.x; KP[d4 + 1][c] = kv.y;
            KP[d4 + 2][c] = kv.z; KP[d4 + 3][c] = kv.w;
            *(float4*)&Vs[c][d4] = *(const float4*)(kp + 1024);
        }
        __syncthreads();

        // S = Q K^T (4x4 register tile)
        float s[4][4];
        #pragma unroll
        for (int i = 0; i < 4; i++)
            #pragma unroll
            for (int j = 0; j < 4; j++) s[i][j] = 0.f;

        #pragma unroll 16
        for (int d = 0; d < 64; d++) {
            float4 a = *(const float4*)&Qs[d][ty * 4];
            float4 k = *(const float4*)&KP[d][tx * 4];
            s[0][0] += a.x * k.x; s[0][1] += a.x * k.y; s[0][2] += a.x * k.z; s[0][3] += a.x * k.w;
            s[1][0] += a.y * k.x; s[1][1] += a.y * k.y; s[1][2] += a.y * k.z; s[1][3] += a.y * k.w;
            s[2][0] += a.z * k.x; s[2][1] += a.z * k.y; s[2][2] += a.z * k.z; s[2][3] += a.z * k.w;
            s[3][0] += a.w * k.x; s[3][1] += a.w * k.y; s[3][2] += a.w * k.z; s[3][3] += a.w * k.w;
        }

        // scale + causal mask (only diagonal chunk needs masking)
        if (kb == bx) {
            #pragma unroll
            for (int i = 0; i < 4; i++)
                #pragma unroll
                for (int j = 0; j < 4; j++)
                    s[i][j] = (tx * 4 + j <= ty * 4 + i) ? s[i][j] * 0.125f : -1e30f;
        } else {
            #pragma unroll
            for (int i = 0; i < 4; i++)
                #pragma unroll
                for (int j = 0; j < 4; j++) s[i][j] *= 0.125f;
        }

        // online softmax: row stats across the 16 threads sharing ty
        float alpha[4];
        #pragma unroll
        for (int i = 0; i < 4; i++) {
            float rm = fmaxf(fmaxf(s[i][0], s[i][1]), fmaxf(s[i][2], s[i][3]));
            #pragma unroll
            for (int off = 8; off > 0; off >>= 1)
                rm = fmaxf(rm, __shfl_xor_sync(0xffffffffu, rm, off));
            float m_new = fmaxf(m[i], rm);
            alpha[i] = expf(m[i] - m_new);
            m[i] = m_new;
            #pragma unroll
            for (int j = 0; j < 4; j++) s[i][j] = expf(s[i][j] - m_new);
            float rl = s[i][0] + s[i][1] + s[i][2] + s[i][3];
            #pragma unroll
            for (int off = 8; off > 0; off >>= 1)
                rl += __shfl_xor_sync(0xffffffffu, rl, off);
            l[i] = l[i] * alpha[i] + rl;
            #pragma unroll
            for (int j = 0; j < 4; j++) o[i][j] *= alpha[i];
        }

        __syncthreads();   // all warps finished reading KP as K

        // store P transposed: KP[k][r]
        #pragma unroll
        for (int i = 0; i < 4; i++)
            #pragma unroll
            for (int j = 0; j < 4; j++)
                KP[tx * 4 + j][ty * 4 + i] = s[i][j];
        __syncthreads();

        // O += P V (4x4 register tile)
        #pragma unroll 16
        for (int k = 0; k < 64; k++) {
            float4 p = *(const float4*)&KP[k][ty * 4];
            float4 v = *(const float4*)&Vs[k][tx * 4];
            o[0][0] += p.x * v.x; o[0][1] += p.x * v.y; o[0][2] += p.x * v.z; o[0][3] += p.x * v.w;
            o[1][0] += p.y * v.x; o[1][1] += p.y * v.y; o[1][2] += p.y * v.z; o[1][3] += p.y * v.w;
            o[2][0] += p.z * v.x; o[2][1] += p.z * v.y; o[2][2] += p.z * v.z; o[2][3] += p.z * v.w;
            o[3][0] += p.w * v.x; o[3][1] += p.w * v.y; o[3][2] += p.w * v.z; o[3][3] += p.w * v.w;
        }
    }

    // epilogue: normalize and store
    #pragma unroll
    for (int i = 0; i < 4; i++) {
        float inv = 1.0f / l[i];
        float4 w = make_float4(o[i][0] * inv, o[i][1] * inv,
                               o[i][2] * inv, o[i][3] * inv);
        *(float4*)(g_att + ((size_t)b * SEQ + q0 + ty * 4 + i) * 1024
                   + h * 64 + tx * 4) = w;
    }
}

// ---------------------------------------------------------------------------
extern "C" void kernel_launch(void* const* d_in, const int* in_sizes, int n_in,
                              void* d_out, int out_size)
{
    const float* x     = (const float*)d_in[0];
    const float* w_qkv = (const float*)d_in[1];
    const float* w_out = (const float*)d_in[2];
    for (int i = 0; i < n_in; i++) {
        if      (in_sizes[i] == M_TOK * D_MODEL)       x     = (const float*)d_in[i];
        else if (in_sizes[i] == 3 * D_MODEL * D_MODEL) w_qkv = (const float*)d_in[i];
        else if (in_sizes[i] == D_MODEL * D_MODEL)     w_out = (const float*)d_in[i];
    }
    float* out = (float*)d_out;

    float *qkv = nullptr, *att = nullptr;
    cudaGetSymbolAddress((void**)&qkv, g_qkv);
    cudaGetSymbolAddress((void**)&att, g_att);

    // 1) QKV projection
    sgemm_nt_128x128<<<dim3(3 * D_MODEL / 128, M_TOK / 128), 256>>>(
        x, w_qkv, qkv, M_TOK, 3 * D_MODEL, D_MODEL);

    // 2) Sign-flipped NeoX RoPE
    rope_kernel<<<(M_TOK * 2 * N_HEADS * 32) / 256, 256>>>();

    // 3) Causal flash attention v2 (GEMM-style register blocking)
    attn_v2<<<dim3(SEQ / 64, BATCH * N_HEADS), 256>>>();

    // 4) Output projection
    sgemm_nt_128x128<<<dim3(D_MODEL / 128, M_TOK / 128), 256>>>(
        att, w_out, out, M_TOK, D_MODEL, D_MODEL);
}

// round 9
// speedup vs baseline: 1.5048x; 1.0770x over previous
#include <cuda_runtime.h>
#include <math.h>

#define D_MODEL  1024
#define N_HEADS  16
#define HEAD_DIM 64
#define BATCH    4
#define SEQ      2048
#define M_TOK    (BATCH * SEQ)   // 8192

// Scratch (allocation-free rule: __device__ globals)
__device__ float g_qkv[(size_t)M_TOK * 3 * D_MODEL];  // 96 MB
__device__ float g_att[(size_t)M_TOK * D_MODEL];      // 32 MB

// ---------------------------------------------------------------------------
// SGEMM: C[M,N] = A[M,K] @ W[N,K]^T (verified == naive in R3)
// ---------------------------------------------------------------------------
__global__ __launch_bounds__(256) void sgemm_nt_128x128(
    const float* __restrict__ A, const float* __restrict__ W,
    float* __restrict__ C, int M, int N, int K)
{
    __shared__ float As[32][132];
    __shared__ float Bs[32][132];

    const int tid = threadIdx.x;
    const int tx  = tid & 15;
    const int ty  = tid >> 4;
    const size_t arow0 = (size_t)blockIdx.y * 128;
    const size_t brow0 = (size_t)blockIdx.x * 128;
    const float* Ab = A + arow0 * (size_t)K;
    const float* Wb = W + brow0 * (size_t)K;

    float acc[8][8];
    #pragma unroll
    for (int i = 0; i < 8; i++)
        #pragma unroll
        for (int j = 0; j < 8; j++) acc[i][j] = 0.f;

    for (int k0 = 0; k0 < K; k0 += 32) {
        #pragma unroll
        for (int i = 0; i < 4; i++) {
            int idx = tid + i * 256;
            int row = idx >> 3;
            int c4  = (idx & 7) * 4;
            float4 va = *(const float4*)(Ab + (size_t)row * K + k0 + c4);
            As[c4 + 0][row] = va.x; As[c4 + 1][row] = va.y;
            As[c4 + 2][row] = va.z; As[c4 + 3][row] = va.w;
            float4 vb = *(const float4*)(Wb + (size_t)row * K + k0 + c4);
            Bs[c4 + 0][row] = vb.x; Bs[c4 + 1][row] = vb.y;
            Bs[c4 + 2][row] = vb.z; Bs[c4 + 3][row] = vb.w;
        }
        __syncthreads();
        #pragma unroll
        for (int kk = 0; kk < 32; kk++) {
            float a[8], b[8];
            *(float4*)&a[0] = *(const float4*)&As[kk][ty * 8];
            *(float4*)&a[4] = *(const float4*)&As[kk][ty * 8 + 4];
            *(float4*)&b[0] = *(const float4*)&Bs[kk][tx * 8];
            *(float4*)&b[4] = *(const float4*)&Bs[kk][tx * 8 + 4];
            #pragma unroll
            for (int i = 0; i < 8; i++)
                #pragma unroll
                for (int j = 0; j < 8; j++)
                    acc[i][j] += a[i] * b[j];
        }
        __syncthreads();
    }

    float* Cb = C + (arow0 + ty * 8) * (size_t)N + brow0 + tx * 8;
    #pragma unroll
    for (int i = 0; i < 8; i++) {
        float4 v0 = make_float4(acc[i][0], acc[i][1], acc[i][2], acc[i][3]);
        float4 v1 = make_float4(acc[i][4], acc[i][5], acc[i][6], acc[i][7]);
        *(float4*)(Cb + (size_t)i * N)     = v0;
        *(float4*)(Cb + (size_t)i * N + 4) = v1;
    }
}

// ---------------------------------------------------------------------------
// RoPE in-place, sign-flipped NeoX (decoded R6, verified R7).
// ---------------------------------------------------------------------------
__global__ __launch_bounds__(256) void rope_kernel()
{
    int idx = blockIdx.x * blockDim.x + threadIdx.x;
    int i   = idx & 31;
    int h   = (idx >> 5) & 15;
    int qk  = (idx >> 9) & 1;
    int tok = idx >> 10;
    int t   = tok & (SEQ - 1);

    double th = pow(10000.0, -(double)i / 32.0);
    float  f  = (float)t * (float)th;
    double cd, sd;
    sincos((double)f, &cd, &sd);
    float c = (float)cd, s = (float)sd;

    float* base = g_qkv + (size_t)tok * 3072 + qk * 1024 + h * 64 + i;
    float x1 = base[0];
    float x2 = base[32];
    base[0]  = x1 * c + x2 * s;
    base[32] = x2 * c - x1 * s;
}

// ---------------------------------------------------------------------------
// Flash attention v3 — XOR-swizzled smem, conflict-free hot loops.
// Layouts (all pitch 64 words, 48 KB total static smem):
//   Qs: Q^T [d][r]  swizzled: word = d*64 + ((rg ^ (d&15))<<2) + (r&3)
//   KT: K^T [d][c]  swizzled same; REUSED as P [r][k] swizzled
//   Vs: V   [k][d]  straight (conflict-free by construction)
// Thread (tx,ty) owns S/O 4x4 tile: rows ty*4.., cols tx*4.. .
// ---------------------------------------------------------------------------
__global__ __launch_bounds__(256) void attn_v3()
{
    __shared__ float Qs[64 * 64];
    __shared__ float KT[64 * 64];
    __shared__ float Vs[64 * 64];

    const int tid = threadIdx.x;
    const int tx  = tid & 15;
    const int ty  = tid >> 4;
    const int bx  = gridDim.x - 1 - blockIdx.x;   // heavy CTAs first
    const int bh  = blockIdx.y;
    const int b   = bh >> 4;
    const int h   = bh & 15;
    const int q0  = bx * 64;
    const size_t base = (size_t)b * SEQ * 3072;

    // Stage Q^T (swizzled transpose store: 4-way max conflict, once per CTA)
    #pragma unroll
    for (int i = 0; i < 4; i++) {
        int idx = tid + i * 256;
        int r   = idx >> 4;
        int d4  = (idx & 15) * 4;
        float4 v = *(const float4*)(g_qkv + base + (size_t)(q0 + r) * 3072 + h * 64 + d4);
        int rg = r >> 2, rw = r & 3;
        Qs[(d4 + 0) * 64 + ((rg ^ ((d4 + 0) & 15)) << 2) + rw] = v.x;
        Qs[(d4 + 1) * 64 + ((rg ^ ((d4 + 1) & 15)) << 2) + rw] = v.y;
        Qs[(d4 + 2) * 64 + ((rg ^ ((d4 + 2) & 15)) << 2) + rw] = v.z;
        Qs[(d4 + 3) * 64 + ((rg ^ ((d4 + 3) & 15)) << 2) + rw] = v.w;
    }

    float o[4][4];
    float m[4], l[4];
    #pragma unroll
    for (int i = 0; i < 4; i++) {
        m[i] = -1e30f; l[i] = 0.f;
        #pragma unroll
        for (int j = 0; j < 4; j++) o[i][j] = 0.f;
    }

    for (int kb = 0; kb <= bx; kb++) {
        const int j0 = kb * 64;
        __syncthreads();   // prev PV done with KT(P)/Vs; Q staged (first iter)

        // Stage K^T (swizzled) and V (straight)
        #pragma unroll
        for (int i = 0; i < 4; i++) {
            int idx = tid + i * 256;
            int c   = idx >> 4;
            int d4  = (idx & 15) * 4;
            const float* kp = g_qkv + base + (size_t)(j0 + c) * 3072 + 1024 + h * 64 + d4;
            float4 kv = *(const float4*)kp;
            float4 vv = *(const float4*)(kp + 1024);
            *(float4*)&Vs[c * 64 + d4] = vv;
            int cg = c >> 2, cw = c & 3;
            KT[(d4 + 0) * 64 + ((cg ^ ((d4 + 0) & 15)) << 2) + cw] = kv.x;
            KT[(d4 + 1) * 64 + ((cg ^ ((d4 + 1) & 15)) << 2) + cw] = kv.y;
            KT[(d4 + 2) * 64 + ((cg ^ ((d4 + 2) & 15)) << 2) + cw] = kv.z;
            KT[(d4 + 3) * 64 + ((cg ^ ((d4 + 3) & 15)) << 2) + cw] = kv.w;
        }
        __syncthreads();

        // S = Q K^T : conflict-free swizzled reads
        float s[4][4];
        #pragma unroll
        for (int i = 0; i < 4; i++)
            #pragma unroll
            for (int j = 0; j < 4; j++) s[i][j] = 0.f;

        #pragma unroll 16
        for (int d = 0; d < 64; d++) {
            int sw = (d & 15);
            float4 a = *(const float4*)&Qs[d * 64 + ((ty ^ sw) << 2)];
            float4 k = *(const float4*)&KT[d * 64 + ((tx ^ sw) << 2)];
            s[0][0] += a.x * k.x; s[0][1] += a.x * k.y; s[0][2] += a.x * k.z; s[0][3] += a.x * k.w;
            s[1][0] += a.y * k.x; s[1][1] += a.y * k.y; s[1][2] += a.y * k.z; s[1][3] += a.y * k.w;
            s[2][0] += a.z * k.x; s[2][1] += a.z * k.y; s[2][2] += a.z * k.z; s[2][3] += a.z * k.w;
            s[3][0] += a.w * k.x; s[3][1] += a.w * k.y; s[3][2] += a.w * k.z; s[3][3] += a.w * k.w;
        }

        // scale + causal mask (diagonal chunk only)
        if (kb == bx) {
            #pragma unroll
            for (int i = 0; i < 4; i++)
                #pragma unroll
                for (int j = 0; j < 4; j++)
                    s[i][j] = (tx * 4 + j <= ty * 4 + i) ? s[i][j] * 0.125f : -1e30f;
        } else {
            #pragma unroll
            for (int i = 0; i < 4; i++)
                #pragma unroll
                for (int j = 0; j < 4; j++) s[i][j] *= 0.125f;
        }

        // online softmax across the 16 tx-lanes of each row
        float alpha[4];
        #pragma unroll
        for (int i = 0; i < 4; i++) {
            float rm = fmaxf(fmaxf(s[i][0], s[i][1]), fmaxf(s[i][2], s[i][3]));
            #pragma unroll
            for (int off = 8; off > 0; off >>= 1)
                rm = fmaxf(rm, __shfl_xor_sync(0xffffffffu, rm, off));
            float m_new = fmaxf(m[i], rm);
            alpha[i] = __expf(m[i] - m_new);
            m[i] = m_new;
            #pragma unroll
            for (int j = 0; j < 4; j++) s[i][j] = __expf(s[i][j] - m_new);
            float rl = s[i][0] + s[i][1] + s[i][2] + s[i][3];
            #pragma unroll
            for (int off = 8; off > 0; off >>= 1)
                rl += __shfl_xor_sync(0xffffffffu, rl, off);
            l[i] = l[i] * alpha[i] + rl;
            #pragma unroll
            for (int j = 0; j < 4; j++) o[i][j] *= alpha[i];
        }

        __syncthreads();   // everyone done reading KT as K

        // store P (swizzled float4, conflict-free): row r, group tx^(r&15)
        #pragma unroll
        for (int i = 0; i < 4; i++) {
            int r = ty * 4 + i;
            *(float4*)&KT[r * 64 + ((tx ^ (r & 15)) << 2)] =
                make_float4(s[i][0], s[i][1], s[i][2], s[i][3]);
        }
        __syncthreads();

        // O += P V  (p reads broadcast; V reads conflict-free)
        #pragma unroll 4
        for (int k4 = 0; k4 < 16; k4++) {
            float4 p[4];
            #pragma unroll
            for (int i = 0; i < 4; i++) {
                int r = ty * 4 + i;
                p[i] = *(const float4*)&KT[r * 64 + ((k4 ^ (r & 15)) << 2)];
            }
            #pragma unroll
            for (int kk = 0; kk < 4; kk++) {
                float4 v = *(const float4*)&Vs[(k4 * 4 + kk) * 64 + tx * 4];
                float p0 = ((const float*)&p[0])[kk];
                float p1 = ((const float*)&p[1])[kk];
                float p2 = ((const float*)&p[2])[kk];
                float p3 = ((const float*)&p[3])[kk];
                o[0][0] += p0 * v.x; o[0][1] += p0 * v.y; o[0][2] += p0 * v.z; o[0][3] += p0 * v.w;
                o[1][0] += p1 * v.x; o[1][1] += p1 * v.y; o[1][2] += p1 * v.z; o[1][3] += p1 * v.w;
                o[2][0] += p2 * v.x; o[2][1] += p2 * v.y; o[2][2] += p2 * v.z; o[2][3] += p2 * v.w;
                o[3][0] += p3 * v.x; o[3][1] += p3 * v.y; o[3][2] += p3 * v.z; o[3][3] += p3 * v.w;
            }
        }
    }

    // epilogue
    #pragma unroll
    for (int i = 0; i < 4; i++) {
        float inv = 1.0f / l[i];
        float4 w = make_float4(o[i][0] * inv, o[i][1] * inv,
                               o[i][2] * inv, o[i][3] * inv);
        *(float4*)(g_att + ((size_t)b * SEQ + q0 + ty * 4 + i) * 1024
                   + h * 64 + tx * 4) = w;
    }
}

// ---------------------------------------------------------------------------
extern "C" void kernel_launch(void* const* d_in, const int* in_sizes, int n_in,
                              void* d_out, int out_size)
{
    const float* x     = (const float*)d_in[0];
    const float* w_qkv = (const float*)d_in[1];
    const float* w_out = (const float*)d_in[2];
    for (int i = 0; i < n_in; i++) {
        if      (in_sizes[i] == M_TOK * D_MODEL)       x     = (const float*)d_in[i];
        else if (in_sizes[i] == 3 * D_MODEL * D_MODEL) w_qkv = (const float*)d_in[i];
        else if (in_sizes[i] == D_MODEL * D_MODEL)     w_out = (const float*)d_in[i];
    }
    float* out = (float*)d_out;

    float *qkv = nullptr, *att = nullptr;
    cudaGetSymbolAddress((void**)&qkv, g_qkv);
    cudaGetSymbolAddress((void**)&att, g_att);

    // 1) QKV projection
    sgemm_nt_128x128<<<dim3(3 * D_MODEL / 128, M_TOK / 128), 256>>>(
        x, w_qkv, qkv, M_TOK, 3 * D_MODEL, D_MODEL);

    // 2) Sign-flipped NeoX RoPE
    rope_kernel<<<(M_TOK * 2 * N_HEADS * 32) / 256, 256>>>();

    // 3) Causal flash attention v3 (swizzled smem)
    attn_v3<<<dim3(SEQ / 64, BATCH * N_HEADS), 256>>>();

    // 4) Output projection
    sgemm_nt_128x128<<<dim3(D_MODEL / 128, M_TOK / 128), 256>>>(
        att, w_out, out, M_TOK, D_MODEL, D_MODEL);
}